// round 15
// baseline (speedup 1.0000x reference)
#include <cuda_runtime.h>
#include <cuda_bf16.h>
#include <math.h>
#include <stdint.h>

// ---------------------------------------------------------------------------
// GPT-2 forward. B=8 T=512 E=1024 H=16 D=64 F=4096 V=512 L=12
// Round 14: term-major MMA ordering (kill accumulator RAW chains);
//           launch order puts QKV GEMM at index 5 so ncu captures it.
// ---------------------------------------------------------------------------

#define EE   1024
#define TT   512
#define BB   8
#define VV   512
#define LL   12
#define FF   4096
#define MR   4096
#define HH   16
#define DD   64
#define QKVW 3072

// ---------------- scratch (device globals; allocation-free rule) -----------
__device__ float g_h  [(size_t)MR * EE];
__device__ float g_qkv[(size_t)MR * QKVW];

__device__ __nv_bfloat16 g_xn_h[(size_t)MR * EE];
__device__ __nv_bfloat16 g_xn_l[(size_t)MR * EE];
__device__ __nv_bfloat16 g_y_h [(size_t)MR * EE];
__device__ __nv_bfloat16 g_y_l [(size_t)MR * EE];
__device__ __nv_bfloat16 g_mlp_h[(size_t)MR * FF];
__device__ __nv_bfloat16 g_mlp_l[(size_t)MR * FF];

// transposed bf16 weights [N][K] per layer, hi/lo
__device__ __nv_bfloat16 g_wqkvT_h[(size_t)LL * QKVW * EE];
__device__ __nv_bfloat16 g_wqkvT_l[(size_t)LL * QKVW * EE];
__device__ __nv_bfloat16 g_wpT_h[(size_t)LL * EE * EE];
__device__ __nv_bfloat16 g_wpT_l[(size_t)LL * EE * EE];
__device__ __nv_bfloat16 g_f1T_h[(size_t)LL * EE * FF];
__device__ __nv_bfloat16 g_f1T_l[(size_t)LL * EE * FF];
__device__ __nv_bfloat16 g_f2T_h[(size_t)LL * EE * FF];
__device__ __nv_bfloat16 g_f2T_l[(size_t)LL * EE * FF];
__device__ __nv_bfloat16 g_hdT_h[(size_t)VV * EE];
__device__ __nv_bfloat16 g_hdT_l[(size_t)VV * EE];

// ---------------------------- PTX helpers ----------------------------------
__device__ __forceinline__ uint32_t smem_u32(const void* p) {
    uint32_t a;
    asm("{ .reg .u64 t; cvta.to.shared.u64 t, %1; cvt.u32.u64 %0, t; }"
        : "=r"(a) : "l"(p));
    return a;
}

__device__ __forceinline__ void cp_async16(uint32_t dst, const void* src) {
    asm volatile("cp.async.cg.shared.global [%0], [%1], 16;"
                 :: "r"(dst), "l"(src));
}
#define CP_COMMIT() asm volatile("cp.async.commit_group;" ::: "memory")
#define CP_WAIT(n)  asm volatile("cp.async.wait_group %0;" :: "n"(n) : "memory")

__device__ __forceinline__ void ldsm4(uint32_t& r0, uint32_t& r1,
                                      uint32_t& r2, uint32_t& r3, uint32_t a) {
    asm volatile("ldmatrix.sync.aligned.m8n8.x4.shared.b16 {%0,%1,%2,%3}, [%4];"
                 : "=r"(r0), "=r"(r1), "=r"(r2), "=r"(r3) : "r"(a));
}

__device__ __forceinline__ void mma16816(float* d,
                                         uint32_t a0, uint32_t a1, uint32_t a2, uint32_t a3,
                                         uint32_t b0, uint32_t b1) {
    asm volatile(
        "mma.sync.aligned.m16n8k16.row.col.f32.bf16.bf16.f32 "
        "{%0,%1,%2,%3}, {%4,%5,%6,%7}, {%8,%9}, {%0,%1,%2,%3};"
        : "+f"(d[0]), "+f"(d[1]), "+f"(d[2]), "+f"(d[3])
        : "r"(a0), "r"(a1), "r"(a2), "r"(a3), "r"(b0), "r"(b1));
}

__device__ __forceinline__ void split_bf16(float v, __nv_bfloat16& hi, __nv_bfloat16& lo) {
    hi = __float2bfloat16(v);
    lo = __float2bfloat16(v - __bfloat162float(hi));
}

// ---------------------------------------------------------------------------
// Embedding
// ---------------------------------------------------------------------------
__global__ void embed_kernel(const int* __restrict__ x,
                             const float* __restrict__ tok,
                             const float* __restrict__ pos,
                             float* __restrict__ h)
{
    int row = blockIdx.x;
    int t   = row & (TT - 1);
    int tk  = x[row];
    const float* te = tok + (size_t)tk * EE;
    const float* pe = pos + (size_t)t  * EE;
    float* hr = h + (size_t)row * EE;
    for (int j = threadIdx.x; j < EE; j += blockDim.x)
        hr[j] = te[j] + pe[j];
}

// ---------------------------------------------------------------------------
// LayerNorm -> bf16 hi/lo outputs
// ---------------------------------------------------------------------------
__global__ void ln_kernel(const float* __restrict__ x,
                          const float* __restrict__ g,
                          const float* __restrict__ b,
                          __nv_bfloat16* __restrict__ oh,
                          __nv_bfloat16* __restrict__ ol)
{
    int row = blockIdx.x;
    const float* xr = x + (size_t)row * EE;
    float s = 0.f, s2 = 0.f;
    for (int j = threadIdx.x; j < EE; j += 256) {
        float v = xr[j];
        s += v; s2 += v * v;
    }
    #pragma unroll
    for (int o = 16; o; o >>= 1) {
        s  += __shfl_xor_sync(0xffffffffu, s,  o);
        s2 += __shfl_xor_sync(0xffffffffu, s2, o);
    }
    __shared__ float sh[2][8];
    int w = threadIdx.x >> 5, lane = threadIdx.x & 31;
    if (lane == 0) { sh[0][w] = s; sh[1][w] = s2; }
    __syncthreads();
    if (w == 0) {
        s  = (lane < 8) ? sh[0][lane] : 0.f;
        s2 = (lane < 8) ? sh[1][lane] : 0.f;
        #pragma unroll
        for (int o = 4; o; o >>= 1) {
            s  += __shfl_xor_sync(0xffffffffu, s,  o);
            s2 += __shfl_xor_sync(0xffffffffu, s2, o);
        }
        if (lane == 0) { sh[0][0] = s; sh[1][0] = s2; }
    }
    __syncthreads();
    s = sh[0][0]; s2 = sh[1][0];
    float mu  = s * (1.f / EE);
    float var = s2 * (1.f / EE) - mu * mu;
    float rs  = rsqrtf(var + 1e-5f);
    size_t ro = (size_t)row * EE;
    for (int j = threadIdx.x; j < EE; j += 256) {
        float vv = (xr[j] - mu) * rs * g[j] + b[j];
        __nv_bfloat16 hi, lo; split_bf16(vv, hi, lo);
        oh[ro + j] = hi; ol[ro + j] = lo;
    }
}

// ---------------------------------------------------------------------------
// Weight convert + transpose: W[K][N] fp32 -> Wt[N][K] bf16 hi/lo.
// grid.z = layer; outLS = per-layer element stride of output buffer.
// ---------------------------------------------------------------------------
__global__ void wconv_kernel(const float* __restrict__ W,
                             __nv_bfloat16* __restrict__ Th,
                             __nv_bfloat16* __restrict__ Tl,
                             int K, int N, size_t outLS)
{
    __shared__ float t[32][33];
    const float* Wl = W + (size_t)blockIdx.z * K * N;
    __nv_bfloat16* Thl = Th + (size_t)blockIdx.z * outLS;
    __nv_bfloat16* Tll = Tl + (size_t)blockIdx.z * outLS;
    int n0 = blockIdx.x * 32, k0 = blockIdx.y * 32;
    int tx = threadIdx.x, ty = threadIdx.y;
    #pragma unroll
    for (int i = 0; i < 4; i++)
        t[ty + i * 8][tx] = Wl[(size_t)(k0 + ty + i * 8) * N + n0 + tx];
    __syncthreads();
    #pragma unroll
    for (int i = 0; i < 4; i++) {
        int r = ty + i * 8;
        float v = t[tx][r];
        __nv_bfloat16 hi, lw; split_bf16(v, hi, lw);
        size_t o = (size_t)(n0 + r) * K + k0 + tx;
        Thl[o] = hi; Tll[o] = lw;
    }
}

// ---------------------------------------------------------------------------
// HMMA GEMM: out = act(A @ Wt^T + bias) (+res)
//   A: [M][K] bf16 hi/lo, Wt: [N][K] bf16 hi/lo (both K-major)
//   3-term: Ah*Bh + Ah*Bl + Al*Bh, fp32 accum, TERM-MAJOR issue order
//   (16 independent MMAs between reuses of any accumulator).
//   CTA 128x256, 8 warps (2x4), warp tile 64x64, BK=32, cp.async 2-stage.
//   biasK/biasV non-null => QKV mode: bias section selected by col>>10.
// ---------------------------------------------------------------------------
#define BK      32
#define ROWB    80
#define A_TILE  (128 * ROWB)
#define B_TILE  (256 * ROWB)
#define OFF_AH  0
#define OFF_AL  A_TILE
#define OFF_BH  (2 * A_TILE)
#define OFF_BL  (2 * A_TILE + B_TILE)
#define STAGE_B (2 * A_TILE + 2 * B_TILE)   // 61440 B
#define GEMM_SMEM (2 * STAGE_B)             // 122880 B

__global__ __launch_bounds__(256)
void mma_gemm(const __nv_bfloat16* __restrict__ Ah, const __nv_bfloat16* __restrict__ Al,
              const __nv_bfloat16* __restrict__ Bh, const __nv_bfloat16* __restrict__ Bl,
              const float* __restrict__ bias,
              const float* __restrict__ biasK, const float* __restrict__ biasV,
              const float* __restrict__ res,
              float* __restrict__ outF,
              __nv_bfloat16* __restrict__ outH, __nv_bfloat16* __restrict__ outL,
              int M, int N, int K, int act)
{
    extern __shared__ char dsm[];
    uint32_t sbase = smem_u32(dsm);

    int tid  = threadIdx.x;
    int wid  = tid >> 5, lane = tid & 31;
    int wm   = wid >> 2;
    int wn   = wid & 3;
    int row0 = blockIdx.y * 128;
    int col0 = blockIdx.x * 256;

    float acc[4][8][4];
    #pragma unroll
    for (int i = 0; i < 4; i++)
        #pragma unroll
        for (int j = 0; j < 8; j++)
            #pragma unroll
            for (int c = 0; c < 4; c++) acc[i][j][c] = 0.f;

    int nch = K / BK;

    #define LOAD_STAGE(stU, kb)                                                   \
    do {                                                                          \
        _Pragma("unroll")                                                         \
        for (int rep = 0; rep < 2; ++rep) {                                       \
            int idx = tid + rep * 256;                                            \
            int r = idx >> 2, u = idx & 3;                                        \
            cp_async16((stU) + OFF_AH + r * ROWB + u * 16,                        \
                       Ah + (size_t)(row0 + r) * K + (kb) + u * 8);               \
            cp_async16((stU) + OFF_AL + r * ROWB + u * 16,                        \
                       Al + (size_t)(row0 + r) * K + (kb) + u * 8);               \
        }                                                                         \
        _Pragma("unroll")                                                         \
        for (int rep = 0; rep < 4; ++rep) {                                       \
            int idx = tid + rep * 256;                                            \
            int r = idx >> 2, u = idx & 3;                                        \
            cp_async16((stU) + OFF_BH + r * ROWB + u * 16,                        \
                       Bh + (size_t)(col0 + r) * K + (kb) + u * 8);               \
            cp_async16((stU) + OFF_BL + r * ROWB + u * 16,                        \
                       Bl + (size_t)(col0 + r) * K + (kb) + u * 8);               \
        }                                                                         \
    } while (0)

    LOAD_STAGE(sbase, 0);
    CP_COMMIT();

    int buf = 0;
    for (int ch = 0; ch < nch; ++ch) {
        if (ch + 1 < nch) {
            uint32_t st = sbase + (buf ^ 1) * STAGE_B;
            LOAD_STAGE(st, (ch + 1) * BK);
            CP_COMMIT();
            CP_WAIT(1);
        } else {
            CP_WAIT(0);
        }
        __syncthreads();

        uint32_t st  = sbase + buf * STAGE_B;
        uint32_t sAh = st + OFF_AH;
        uint32_t sAl = st + OFF_AL;
        uint32_t sBh = st + OFF_BH;
        uint32_t sBl = st + OFF_BL;

        #pragma unroll
        for (int ks = 0; ks < 2; ++ks) {
            uint32_t ah[4][4], al[4][4];
            int ar  = (lane & 15);
            int akb = ks * 16 + ((lane >> 4) << 3);
            #pragma unroll
            for (int im = 0; im < 4; ++im) {
                uint32_t off = (uint32_t)(wm * 64 + im * 16 + ar) * ROWB + akb * 2;
                ldsm4(ah[im][0], ah[im][1], ah[im][2], ah[im][3], sAh + off);
                ldsm4(al[im][0], al[im][1], al[im][2], al[im][3], sAl + off);
            }
            #pragma unroll
            for (int jb = 0; jb < 8; jb += 4) {
                uint32_t bh[4][2], bl[4][2];
                #pragma unroll
                for (int p = 0; p < 2; ++p) {
                    int j0 = jb + 2 * p;
                    int n  = wn * 64 + (j0 + ((lane >> 4) & 1)) * 8 + (lane & 7);
                    int kc = ks * 16 + (((lane >> 3) & 1) << 3);
                    uint32_t off = (uint32_t)n * ROWB + kc * 2;
                    ldsm4(bh[2*p][0], bh[2*p][1], bh[2*p+1][0], bh[2*p+1][1], sBh + off);
                    ldsm4(bl[2*p][0], bl[2*p][1], bl[2*p+1][0], bl[2*p+1][1], sBl + off);
                }
                // TERM-MAJOR: 16 independent MMAs per term; accumulator reuse
                // distance = 16 -> no RAW-stall chains.
                #pragma unroll
                for (int im = 0; im < 4; ++im)
                    #pragma unroll
                    for (int jj = 0; jj < 4; ++jj)
                        mma16816(acc[im][jb + jj],
                                 ah[im][0], ah[im][1], ah[im][2], ah[im][3],
                                 bh[jj][0], bh[jj][1]);
                #pragma unroll
                for (int im = 0; im < 4; ++im)
                    #pragma unroll
                    for (int jj = 0; jj < 4; ++jj)
                        mma16816(acc[im][jb + jj],
                                 ah[im][0], ah[im][1], ah[im][2], ah[im][3],
                                 bl[jj][0], bl[jj][1]);
                #pragma unroll
                for (int im = 0; im < 4; ++im)
                    #pragma unroll
                    for (int jj = 0; jj < 4; ++jj)
                        mma16816(acc[im][jb + jj],
                                 al[im][0], al[im][1], al[im][2], al[im][3],
                                 bh[jj][0], bh[jj][1]);
            }
        }
        __syncthreads();
        buf ^= 1;
    }

    // ---- epilogue ----
    int gid = lane >> 2, tig = lane & 3;
    #pragma unroll
    for (int im = 0; im < 4; ++im) {
        #pragma unroll
        for (int j = 0; j < 8; ++j) {
            int col = col0 + wn * 64 + j * 8 + tig * 2;
            const float* bp_ = bias;
            int colb = col;
            if (biasK) {                       // fused-QKV bias select
                int sec = col >> 10;
                bp_  = (sec == 0) ? bias : (sec == 1) ? biasK : biasV;
                colb = col & 1023;
            }
            #pragma unroll
            for (int hr = 0; hr < 2; ++hr) {
                int row = row0 + wm * 64 + im * 16 + gid + hr * 8;
                float v0 = acc[im][j][hr * 2 + 0];
                float v1 = acc[im][j][hr * 2 + 1];
                size_t off = (size_t)row * N + col;
                if (bp_) { v0 += bp_[colb]; v1 += bp_[colb + 1]; }
                if (act == 1) {
                    v0 = 0.5f * v0 * (1.f + erff(v0 * 0.70710678118654752f));
                    v1 = 0.5f * v1 * (1.f + erff(v1 * 0.70710678118654752f));
                }
                if (res) { v0 += res[off]; v1 += res[off + 1]; }
                if (outF) {
                    float2 ov; ov.x = v0; ov.y = v1;
                    *(float2*)(outF + off) = ov;
                }
                if (outH) {
                    __nv_bfloat16 h0, l0, h1, l1;
                    split_bf16(v0, h0, l0);
                    split_bf16(v1, h1, l1);
                    __nv_bfloat162 hv; hv.x = h0; hv.y = h1;
                    __nv_bfloat162 lv; lv.x = l0; lv.y = l1;
                    *(__nv_bfloat162*)(outH + off) = hv;
                    *(__nv_bfloat162*)(outL + off) = lv;
                }
            }
        }
    }
}

// ---------------------------------------------------------------------------
// Attention over fused qkv buffer -> y as bf16 hi/lo
// ---------------------------------------------------------------------------
#define AQ 8

__global__ __launch_bounds__(256)
void attn_kernel(const float* __restrict__ qkv,
                 __nv_bfloat16* __restrict__ yh, __nv_bfloat16* __restrict__ yl)
{
    int qt = blockIdx.x & 63;
    int bh = blockIdx.x >> 6;
    int h_ = bh & (HH - 1);
    int b  = bh >> 4;
    int q0 = qt * AQ;
    size_t baseRow = (size_t)b * TT;
    int colOff = h_ * DD;

    const float* q = qkv + colOff;
    const float* k = qkv + EE + colOff;
    const float* v = qkv + 2 * EE + colOff;

    __shared__ float Qs[AQ][DD];
    __shared__ float S [AQ][TT];
    __shared__ float Tl[DD][68];

    int tid  = threadIdx.x;
    int lane = tid & 31;
    int wq   = tid >> 5;
    const float scale = 0.125f;

    for (int idx = tid; idx < AQ * DD; idx += 256) {
        int qi = idx >> 6, d = idx & 63;
        Qs[qi][d] = q[(baseRow + q0 + qi) * QKVW + d] * scale;
    }

    int qmaxg  = q0 + AQ - 1;
    int ntiles = (qmaxg >> 6) + 1;

    for (int kt = 0; kt < ntiles; ++kt) {
        int k0 = kt * 64;
        __syncthreads();
        for (int f = tid; f < 64 * 16; f += 256) {
            int kk = f >> 4, c4 = (f & 15) * 4;
            float4 kv = *(const float4*)(k + (baseRow + k0 + kk) * QKVW + c4);
            Tl[c4 + 0][kk] = kv.x;
            Tl[c4 + 1][kk] = kv.y;
            Tl[c4 + 2][kk] = kv.z;
            Tl[c4 + 3][kk] = kv.w;
        }
        __syncthreads();
        float s0 = 0.f, s1 = 0.f;
        #pragma unroll 16
        for (int d = 0; d < DD; ++d) {
            float qv = Qs[wq][d];
            s0 = fmaf(qv, Tl[d][lane],      s0);
            s1 = fmaf(qv, Tl[d][lane + 32], s1);
        }
        int qg = q0 + wq;
        S[wq][k0 + lane]      = (k0 + lane      <= qg) ? s0 : -INFINITY;
        S[wq][k0 + lane + 32] = (k0 + lane + 32 <= qg) ? s1 : -INFINITY;
    }
    __syncthreads();

    {
        int kmaxb = ntiles * 64;
        float m = -INFINITY;
        for (int kk = lane; kk < kmaxb; kk += 32) m = fmaxf(m, S[wq][kk]);
        #pragma unroll
        for (int o = 16; o; o >>= 1) m = fmaxf(m, __shfl_xor_sync(0xffffffffu, m, o));
        float sum = 0.f;
        for (int kk = lane; kk < kmaxb; kk += 32) {
            float e = __expf(S[wq][kk] - m);
            S[wq][kk] = e;
            sum += e;
        }
        #pragma unroll
        for (int o = 16; o; o >>= 1) sum += __shfl_xor_sync(0xffffffffu, sum, o);
        float inv = 1.f / sum;
        for (int kk = lane; kk < kmaxb; kk += 32) S[wq][kk] *= inv;
    }
    __syncthreads();

    float y0 = 0.f, y1 = 0.f;
    for (int kt = 0; kt < ntiles; ++kt) {
        int k0 = kt * 64;
        for (int f = tid; f < 64 * 16; f += 256) {
            int kk = f >> 4, c4 = (f & 15) * 4;
            float4 vv = *(const float4*)(v + (baseRow + k0 + kk) * QKVW + c4);
            *(float4*)&Tl[kk][c4] = vv;
        }
        __syncthreads();
        #pragma unroll 16
        for (int kk = 0; kk < 64; ++kk) {
            float p = S[wq][k0 + kk];
            y0 = fmaf(p, Tl[kk][lane],      y0);
            y1 = fmaf(p, Tl[kk][lane + 32], y1);
        }
        __syncthreads();
    }
    size_t o0 = (baseRow + q0 + wq) * EE + colOff + lane;
    __nv_bfloat16 h0, l0, h1, l1;
    split_bf16(y0, h0, l0);
    split_bf16(y1, h1, l1);
    yh[o0]      = h0; yl[o0]      = l0;
    yh[o0 + 32] = h1; yl[o0 + 32] = l1;
}

// ---------------------------------------------------------------------------
// Launch
// ---------------------------------------------------------------------------
extern "C" void kernel_launch(void* const* d_in, const int* in_sizes, int n_in,
                              void* d_out, int out_size)
{
    const int*   x     = (const int*)  d_in[0];
    const float* tok   = (const float*)d_in[2];
    const float* pos   = (const float*)d_in[3];
    const float* ln1g  = (const float*)d_in[4];
    const float* ln1b  = (const float*)d_in[5];
    const float* Wq    = (const float*)d_in[6];
    const float* bq    = (const float*)d_in[7];
    const float* Wk    = (const float*)d_in[8];
    const float* bk    = (const float*)d_in[9];
    const float* Wv    = (const float*)d_in[10];
    const float* bv    = (const float*)d_in[11];
    const float* Wp    = (const float*)d_in[12];
    const float* bp    = (const float*)d_in[13];
    const float* ln2g  = (const float*)d_in[14];
    const float* ln2b  = (const float*)d_in[15];
    const float* Wf1   = (const float*)d_in[16];
    const float* bf1   = (const float*)d_in[17];
    const float* Wf2   = (const float*)d_in[18];
    const float* bf2   = (const float*)d_in[19];
    const float* lnfg  = (const float*)d_in[20];
    const float* lnfb  = (const float*)d_in[21];
    const float* headw = (const float*)d_in[22];
    float* out = (float*)d_out;

    float *h, *qkv;
    cudaGetSymbolAddress((void**)&h,   g_h);
    cudaGetSymbolAddress((void**)&qkv, g_qkv);
    __nv_bfloat16 *xnh, *xnl, *yh, *yl, *mh, *ml;
    cudaGetSymbolAddress((void**)&xnh, g_xn_h);
    cudaGetSymbolAddress((void**)&xnl, g_xn_l);
    cudaGetSymbolAddress((void**)&yh,  g_y_h);
    cudaGetSymbolAddress((void**)&yl,  g_y_l);
    cudaGetSymbolAddress((void**)&mh,  g_mlp_h);
    cudaGetSymbolAddress((void**)&ml,  g_mlp_l);
    __nv_bfloat16 *wqkvh, *wqkvl, *wph, *wpl;
    __nv_bfloat16 *f1h, *f1l, *f2h, *f2l, *hdh, *hdl;
    cudaGetSymbolAddress((void**)&wqkvh, g_wqkvT_h);
    cudaGetSymbolAddress((void**)&wqkvl, g_wqkvT_l);
    cudaGetSymbolAddress((void**)&wph, g_wpT_h); cudaGetSymbolAddress((void**)&wpl, g_wpT_l);
    cudaGetSymbolAddress((void**)&f1h, g_f1T_h); cudaGetSymbolAddress((void**)&f1l, g_f1T_l);
    cudaGetSymbolAddress((void**)&f2h, g_f2T_h); cudaGetSymbolAddress((void**)&f2l, g_f2T_l);
    cudaGetSymbolAddress((void**)&hdh, g_hdT_h); cudaGetSymbolAddress((void**)&hdl, g_hdT_l);

    cudaFuncSetAttribute(mma_gemm, cudaFuncAttributeMaxDynamicSharedMemorySize, GEMM_SMEM);

    const size_t QLS = (size_t)QKVW * EE;
    dim3 wb(32, 8);
    dim3 gQKV(QKVW / 256, MR / 128);
    dim3 gE  (EE   / 256, MR / 128);
    dim3 gF  (FF   / 256, MR / 128);
    dim3 gHd (VV   / 256, MR / 128);

    // ---- launch order chosen so ncu (-s 5 -c 1) captures the QKV GEMM ----
    embed_kernel<<<MR, 256>>>(x, tok, pos, h);                              // 0
    ln_kernel<<<MR, 256>>>(h, ln1g, ln1b, xnh, xnl);                        // 1
    wconv_kernel<<<dim3(EE / 32, EE / 32, LL), wb>>>(Wq, wqkvh + 0 * (size_t)EE * EE,
                                                     wqkvl + 0 * (size_t)EE * EE, EE, EE, QLS);  // 2
    wconv_kernel<<<dim3(EE / 32, EE / 32, LL), wb>>>(Wk, wqkvh + 1 * (size_t)EE * EE,
                                                     wqkvl + 1 * (size_t)EE * EE, EE, EE, QLS);  // 3
    wconv_kernel<<<dim3(EE / 32, EE / 32, LL), wb>>>(Wv, wqkvh + 2 * (size_t)EE * EE,
                                                     wqkvl + 2 * (size_t)EE * EE, EE, EE, QLS);  // 4
    // layer 0 QKV GEMM = launch index 5 (ncu capture target)
    mma_gemm<<<gQKV, 256, GEMM_SMEM>>>(xnh, xnl, wqkvh, wqkvl,
                                       bq, bk, bv, nullptr, qkv, nullptr, nullptr,
                                       MR, QKVW, EE, 0);                    // 5
    // remaining weight conversions
    wconv_kernel<<<dim3(EE / 32, EE / 32, LL), wb>>>(Wp,  wph, wpl, EE, EE, (size_t)EE * EE);
    wconv_kernel<<<dim3(FF / 32, EE / 32, LL), wb>>>(Wf1, f1h, f1l, EE, FF, (size_t)EE * FF);
    wconv_kernel<<<dim3(EE / 32, FF / 32, LL), wb>>>(Wf2, f2h, f2l, FF, EE, (size_t)EE * FF);
    wconv_kernel<<<dim3(VV / 32, EE / 32, 1 ), wb>>>(headw, hdh, hdl, EE, VV, (size_t)EE * VV);

    for (int l = 0; l < LL; ++l) {
        size_t oE  = (size_t)l * EE;
        size_t oQW = (size_t)l * QLS;
        size_t oEE = (size_t)l * EE * EE;
        size_t oF  = (size_t)l * FF;
        size_t oEF = (size_t)l * EE * FF;

        if (l > 0) {
            ln_kernel<<<MR, 256>>>(h, ln1g + oE, ln1b + oE, xnh, xnl);
            mma_gemm<<<gQKV, 256, GEMM_SMEM>>>(xnh, xnl, wqkvh + oQW, wqkvl + oQW,
                                               bq + oE, bk + oE, bv + oE,
                                               nullptr, qkv, nullptr, nullptr,
                                               MR, QKVW, EE, 0);
        }

        attn_kernel<<<BB * HH * (TT / AQ), 256>>>(qkv, yh, yl);

        // h = h + y @ Wp + bp
        mma_gemm<<<gE, 256, GEMM_SMEM>>>(yh, yl, wph + oEE, wpl + oEE,
                                         bp + oE, nullptr, nullptr, h, h,
                                         nullptr, nullptr, MR, EE, EE, 0);

        ln_kernel<<<MR, 256>>>(h, ln2g + oE, ln2b + oE, xnh, xnl);

        // mlp = gelu(xn @ Wf1 + bf1)  -> bf16 hi/lo
        mma_gemm<<<gF, 256, GEMM_SMEM>>>(xnh, xnl, f1h + oEF, f1l + oEF,
                                         bf1 + oF, nullptr, nullptr, nullptr,
                                         nullptr, mh, ml, MR, FF, EE, 1);

        // h = h + mlp @ Wf2 + bf2
        mma_gemm<<<gE, 256, GEMM_SMEM>>>(mh, ml, f2h + oEF, f2l + oEF,
                                         bf2 + oE, nullptr, nullptr, h, h,
                                         nullptr, nullptr, MR, EE, FF, 0);
    }

    ln_kernel<<<MR, 256>>>(h, lnfg, lnfb, xnh, xnl);
    mma_gemm<<<gHd, 256, GEMM_SMEM>>>(xnh, xnl, hdh, hdl,
                                      nullptr, nullptr, nullptr, nullptr,
                                      out, nullptr, nullptr, MR, VV, EE, 0);
}

// round 17
// speedup vs baseline: 1.1732x; 1.1732x over previous
#include <cuda_runtime.h>
#include <cuda_fp16.h>
#include <math.h>
#include <stdint.h>

// ---------------------------------------------------------------------------
// GPT-2 forward. B=8 T=512 E=1024 H=16 D=64 F=4096 V=512 L=12
// Round 16: fp16 2-term split (Ah*B + Al*B). HMMA instr count -33%.
//   Evidence: GEMM time invariant to tile shape/order -> HMMA issue-rate
//   saturated; only fewer instructions can help.
// ---------------------------------------------------------------------------

#define EE   1024
#define TT   512
#define BB   8
#define VV   512
#define LL   12
#define FF   4096
#define MR   4096
#define HH   16
#define DD   64
#define QKVW 3072

// ---------------- scratch (device globals; allocation-free rule) -----------
__device__ float g_h  [(size_t)MR * EE];
__device__ float g_qkv[(size_t)MR * QKVW];

__device__ __half g_xn_h[(size_t)MR * EE];
__device__ __half g_xn_l[(size_t)MR * EE];
__device__ __half g_y_h [(size_t)MR * EE];
__device__ __half g_y_l [(size_t)MR * EE];
__device__ __half g_mlp_h[(size_t)MR * FF];
__device__ __half g_mlp_l[(size_t)MR * FF];

// transposed fp16 weights [N][K] per layer (single precision copy)
__device__ __half g_wqkvT[(size_t)LL * QKVW * EE];
__device__ __half g_wpT  [(size_t)LL * EE * EE];
__device__ __half g_f1T  [(size_t)LL * EE * FF];
__device__ __half g_f2T  [(size_t)LL * EE * FF];
__device__ __half g_hdT  [(size_t)VV * EE];

// ---------------------------- PTX helpers ----------------------------------
__device__ __forceinline__ uint32_t smem_u32(const void* p) {
    uint32_t a;
    asm("{ .reg .u64 t; cvta.to.shared.u64 t, %1; cvt.u32.u64 %0, t; }"
        : "=r"(a) : "l"(p));
    return a;
}

__device__ __forceinline__ void cp_async16(uint32_t dst, const void* src) {
    asm volatile("cp.async.cg.shared.global [%0], [%1], 16;"
                 :: "r"(dst), "l"(src));
}
#define CP_COMMIT() asm volatile("cp.async.commit_group;" ::: "memory")
#define CP_WAIT(n)  asm volatile("cp.async.wait_group %0;" :: "n"(n) : "memory")

__device__ __forceinline__ void ldsm4(uint32_t& r0, uint32_t& r1,
                                      uint32_t& r2, uint32_t& r3, uint32_t a) {
    asm volatile("ldmatrix.sync.aligned.m8n8.x4.shared.b16 {%0,%1,%2,%3}, [%4];"
                 : "=r"(r0), "=r"(r1), "=r"(r2), "=r"(r3) : "r"(a));
}

__device__ __forceinline__ void mma16816(float* d,
                                         uint32_t a0, uint32_t a1, uint32_t a2, uint32_t a3,
                                         uint32_t b0, uint32_t b1) {
    asm volatile(
        "mma.sync.aligned.m16n8k16.row.col.f32.f16.f16.f32 "
        "{%0,%1,%2,%3}, {%4,%5,%6,%7}, {%8,%9}, {%0,%1,%2,%3};"
        : "+f"(d[0]), "+f"(d[1]), "+f"(d[2]), "+f"(d[3])
        : "r"(a0), "r"(a1), "r"(a2), "r"(a3), "r"(b0), "r"(b1));
}

__device__ __forceinline__ void split_f16(float v, __half& hi, __half& lo) {
    hi = __float2half_rn(v);
    lo = __float2half_rn(v - __half2float(hi));
}

// ---------------------------------------------------------------------------
// Embedding
// ---------------------------------------------------------------------------
__global__ void embed_kernel(const int* __restrict__ x,
                             const float* __restrict__ tok,
                             const float* __restrict__ pos,
                             float* __restrict__ h)
{
    int row = blockIdx.x;
    int t   = row & (TT - 1);
    int tk  = x[row];
    const float* te = tok + (size_t)tk * EE;
    const float* pe = pos + (size_t)t  * EE;
    float* hr = h + (size_t)row * EE;
    for (int j = threadIdx.x; j < EE; j += blockDim.x)
        hr[j] = te[j] + pe[j];
}

// ---------------------------------------------------------------------------
// LayerNorm -> fp16 hi/lo outputs
// ---------------------------------------------------------------------------
__global__ void ln_kernel(const float* __restrict__ x,
                          const float* __restrict__ g,
                          const float* __restrict__ b,
                          __half* __restrict__ oh,
                          __half* __restrict__ ol)
{
    int row = blockIdx.x;
    const float* xr = x + (size_t)row * EE;
    float s = 0.f, s2 = 0.f;
    for (int j = threadIdx.x; j < EE; j += 256) {
        float v = xr[j];
        s += v; s2 += v * v;
    }
    #pragma unroll
    for (int o = 16; o; o >>= 1) {
        s  += __shfl_xor_sync(0xffffffffu, s,  o);
        s2 += __shfl_xor_sync(0xffffffffu, s2, o);
    }
    __shared__ float sh[2][8];
    int w = threadIdx.x >> 5, lane = threadIdx.x & 31;
    if (lane == 0) { sh[0][w] = s; sh[1][w] = s2; }
    __syncthreads();
    if (w == 0) {
        s  = (lane < 8) ? sh[0][lane] : 0.f;
        s2 = (lane < 8) ? sh[1][lane] : 0.f;
        #pragma unroll
        for (int o = 4; o; o >>= 1) {
            s  += __shfl_xor_sync(0xffffffffu, s,  o);
            s2 += __shfl_xor_sync(0xffffffffu, s2, o);
        }
        if (lane == 0) { sh[0][0] = s; sh[1][0] = s2; }
    }
    __syncthreads();
    s = sh[0][0]; s2 = sh[1][0];
    float mu  = s * (1.f / EE);
    float var = s2 * (1.f / EE) - mu * mu;
    float rs  = rsqrtf(var + 1e-5f);
    size_t ro = (size_t)row * EE;
    for (int j = threadIdx.x; j < EE; j += 256) {
        float vv = (xr[j] - mu) * rs * g[j] + b[j];
        __half hi, lo; split_f16(vv, hi, lo);
        oh[ro + j] = hi; ol[ro + j] = lo;
    }
}

// ---------------------------------------------------------------------------
// Weight convert + transpose: W[K][N] fp32 -> Wt[N][K] fp16 (single).
// grid.z = layer; outLS = per-layer element stride of output buffer.
// ---------------------------------------------------------------------------
__global__ void wconv_kernel(const float* __restrict__ W,
                             __half* __restrict__ Th,
                             int K, int N, size_t outLS)
{
    __shared__ float t[32][33];
    const float* Wl = W + (size_t)blockIdx.z * K * N;
    __half* Thl = Th + (size_t)blockIdx.z * outLS;
    int n0 = blockIdx.x * 32, k0 = blockIdx.y * 32;
    int tx = threadIdx.x, ty = threadIdx.y;
    #pragma unroll
    for (int i = 0; i < 4; i++)
        t[ty + i * 8][tx] = Wl[(size_t)(k0 + ty + i * 8) * N + n0 + tx];
    __syncthreads();
    #pragma unroll
    for (int i = 0; i < 4; i++) {
        int r = ty + i * 8;
        Thl[(size_t)(n0 + r) * K + k0 + tx] = __float2half_rn(t[tx][r]);
    }
}

// ---------------------------------------------------------------------------
// HMMA GEMM: out = act(A @ Wt^T + bias) (+res)
//   A: [M][K] fp16 hi/lo, Wt: [N][K] fp16 single (both K-major)
//   2-term: Ah*B + Al*B, fp32 accum, term-major issue order.
//   CTA 128x256, 8 warps (2x4), warp tile 64x64, BK=32, cp.async 2-stage.
//   biasK/biasV non-null => QKV mode: bias section selected by col>>10.
// ---------------------------------------------------------------------------
#define BK      32
#define ROWB    80
#define A_TILE  (128 * ROWB)
#define B_TILE  (256 * ROWB)
#define OFF_AH  0
#define OFF_AL  A_TILE
#define OFF_BB  (2 * A_TILE)
#define STAGE_B (2 * A_TILE + B_TILE)       // 40960 B
#define GEMM_SMEM (2 * STAGE_B)             // 81920 B -> 2 CTAs/SM

__global__ __launch_bounds__(256)
void mma_gemm(const __half* __restrict__ Ah, const __half* __restrict__ Al,
              const __half* __restrict__ Bw,
              const float* __restrict__ bias,
              const float* __restrict__ biasK, const float* __restrict__ biasV,
              const float* __restrict__ res,
              float* __restrict__ outF,
              __half* __restrict__ outH, __half* __restrict__ outL,
              int M, int N, int K, int act)
{
    extern __shared__ char dsm[];
    uint32_t sbase = smem_u32(dsm);

    int tid  = threadIdx.x;
    int wid  = tid >> 5, lane = tid & 31;
    int wm   = wid >> 2;
    int wn   = wid & 3;
    int row0 = blockIdx.y * 128;
    int col0 = blockIdx.x * 256;

    float acc[4][8][4];
    #pragma unroll
    for (int i = 0; i < 4; i++)
        #pragma unroll
        for (int j = 0; j < 8; j++)
            #pragma unroll
            for (int c = 0; c < 4; c++) acc[i][j][c] = 0.f;

    int nch = K / BK;

    #define LOAD_STAGE(stU, kb)                                                   \
    do {                                                                          \
        _Pragma("unroll")                                                         \
        for (int rep = 0; rep < 2; ++rep) {                                       \
            int idx = tid + rep * 256;                                            \
            int r = idx >> 2, u = idx & 3;                                        \
            cp_async16((stU) + OFF_AH + r * ROWB + u * 16,                        \
                       Ah + (size_t)(row0 + r) * K + (kb) + u * 8);               \
            cp_async16((stU) + OFF_AL + r * ROWB + u * 16,                        \
                       Al + (size_t)(row0 + r) * K + (kb) + u * 8);               \
        }                                                                         \
        _Pragma("unroll")                                                         \
        for (int rep = 0; rep < 4; ++rep) {                                       \
            int idx = tid + rep * 256;                                            \
            int r = idx >> 2, u = idx & 3;                                        \
            cp_async16((stU) + OFF_BB + r * ROWB + u * 16,                        \
                       Bw + (size_t)(col0 + r) * K + (kb) + u * 8);               \
        }                                                                         \
    } while (0)

    LOAD_STAGE(sbase, 0);
    CP_COMMIT();

    int buf = 0;
    for (int ch = 0; ch < nch; ++ch) {
        if (ch + 1 < nch) {
            uint32_t st = sbase + (buf ^ 1) * STAGE_B;
            LOAD_STAGE(st, (ch + 1) * BK);
            CP_COMMIT();
            CP_WAIT(1);
        } else {
            CP_WAIT(0);
        }
        __syncthreads();

        uint32_t st  = sbase + buf * STAGE_B;
        uint32_t sAh = st + OFF_AH;
        uint32_t sAl = st + OFF_AL;
        uint32_t sB  = st + OFF_BB;

        #pragma unroll
        for (int ks = 0; ks < 2; ++ks) {
            uint32_t ah[4][4], al[4][4];
            int ar  = (lane & 15);
            int akb = ks * 16 + ((lane >> 4) << 3);
            #pragma unroll
            for (int im = 0; im < 4; ++im) {
                uint32_t off = (uint32_t)(wm * 64 + im * 16 + ar) * ROWB + akb * 2;
                ldsm4(ah[im][0], ah[im][1], ah[im][2], ah[im][3], sAh + off);
                ldsm4(al[im][0], al[im][1], al[im][2], al[im][3], sAl + off);
            }
            #pragma unroll
            for (int jb = 0; jb < 8; jb += 4) {
                uint32_t bf[4][2];
                #pragma unroll
                for (int p = 0; p < 2; ++p) {
                    int j0 = jb + 2 * p;
                    int n  = wn * 64 + (j0 + ((lane >> 4) & 1)) * 8 + (lane & 7);
                    int kc = ks * 16 + (((lane >> 3) & 1) << 3);
                    uint32_t off = (uint32_t)n * ROWB + kc * 2;
                    ldsm4(bf[2*p][0], bf[2*p][1], bf[2*p+1][0], bf[2*p+1][1], sB + off);
                }
                // term-major: 16 independent MMAs per term
                #pragma unroll
                for (int im = 0; im < 4; ++im)
                    #pragma unroll
                    for (int jj = 0; jj < 4; ++jj)
                        mma16816(acc[im][jb + jj],
                                 ah[im][0], ah[im][1], ah[im][2], ah[im][3],
                                 bf[jj][0], bf[jj][1]);
                #pragma unroll
                for (int im = 0; im < 4; ++im)
                    #pragma unroll
                    for (int jj = 0; jj < 4; ++jj)
                        mma16816(acc[im][jb + jj],
                                 al[im][0], al[im][1], al[im][2], al[im][3],
                                 bf[jj][0], bf[jj][1]);
            }
        }
        __syncthreads();
        buf ^= 1;
    }

    // ---- epilogue ----
    int gid = lane >> 2, tig = lane & 3;
    #pragma unroll
    for (int im = 0; im < 4; ++im) {
        #pragma unroll
        for (int j = 0; j < 8; ++j) {
            int col = col0 + wn * 64 + j * 8 + tig * 2;
            const float* bp_ = bias;
            int colb = col;
            if (biasK) {                       // fused-QKV bias select
                int sec = col >> 10;
                bp_  = (sec == 0) ? bias : (sec == 1) ? biasK : biasV;
                colb = col & 1023;
            }
            #pragma unroll
            for (int hr = 0; hr < 2; ++hr) {
                int row = row0 + wm * 64 + im * 16 + gid + hr * 8;
                float v0 = acc[im][j][hr * 2 + 0];
                float v1 = acc[im][j][hr * 2 + 1];
                size_t off = (size_t)row * N + col;
                if (bp_) { v0 += bp_[colb]; v1 += bp_[colb + 1]; }
                if (act == 1) {
                    v0 = 0.5f * v0 * (1.f + erff(v0 * 0.70710678118654752f));
                    v1 = 0.5f * v1 * (1.f + erff(v1 * 0.70710678118654752f));
                }
                if (res) { v0 += res[off]; v1 += res[off + 1]; }
                if (outF) {
                    float2 ov; ov.x = v0; ov.y = v1;
                    *(float2*)(outF + off) = ov;
                }
                if (outH) {
                    __half h0, l0, h1, l1;
                    split_f16(v0, h0, l0);
                    split_f16(v1, h1, l1);
                    *(__half2*)(outH + off) = __halves2half2(h0, h1);
                    *(__half2*)(outL + off) = __halves2half2(l0, l1);
                }
            }
        }
    }
}

// ---------------------------------------------------------------------------
// Attention over fused qkv buffer -> y as fp16 hi/lo
// ---------------------------------------------------------------------------
#define AQ 8

__global__ __launch_bounds__(256)
void attn_kernel(const float* __restrict__ qkv,
                 __half* __restrict__ yh, __half* __restrict__ yl)
{
    int qt = blockIdx.x & 63;
    int bh = blockIdx.x >> 6;
    int h_ = bh & (HH - 1);
    int b  = bh >> 4;
    int q0 = qt * AQ;
    size_t baseRow = (size_t)b * TT;
    int colOff = h_ * DD;

    const float* q = qkv + colOff;
    const float* k = qkv + EE + colOff;
    const float* v = qkv + 2 * EE + colOff;

    __shared__ float Qs[AQ][DD];
    __shared__ float S [AQ][TT];
    __shared__ float Tl[DD][68];

    int tid  = threadIdx.x;
    int lane = tid & 31;
    int wq   = tid >> 5;
    const float scale = 0.125f;

    for (int idx = tid; idx < AQ * DD; idx += 256) {
        int qi = idx >> 6, d = idx & 63;
        Qs[qi][d] = q[(baseRow + q0 + qi) * QKVW + d] * scale;
    }

    int qmaxg  = q0 + AQ - 1;
    int ntiles = (qmaxg >> 6) + 1;

    for (int kt = 0; kt < ntiles; ++kt) {
        int k0 = kt * 64;
        __syncthreads();
        for (int f = tid; f < 64 * 16; f += 256) {
            int kk = f >> 4, c4 = (f & 15) * 4;
            float4 kv = *(const float4*)(k + (baseRow + k0 + kk) * QKVW + c4);
            Tl[c4 + 0][kk] = kv.x;
            Tl[c4 + 1][kk] = kv.y;
            Tl[c4 + 2][kk] = kv.z;
            Tl[c4 + 3][kk] = kv.w;
        }
        __syncthreads();
        float s0 = 0.f, s1 = 0.f;
        #pragma unroll 16
        for (int d = 0; d < DD; ++d) {
            float qv = Qs[wq][d];
            s0 = fmaf(qv, Tl[d][lane],      s0);
            s1 = fmaf(qv, Tl[d][lane + 32], s1);
        }
        int qg = q0 + wq;
        S[wq][k0 + lane]      = (k0 + lane      <= qg) ? s0 : -INFINITY;
        S[wq][k0 + lane + 32] = (k0 + lane + 32 <= qg) ? s1 : -INFINITY;
    }
    __syncthreads();

    {
        int kmaxb = ntiles * 64;
        float m = -INFINITY;
        for (int kk = lane; kk < kmaxb; kk += 32) m = fmaxf(m, S[wq][kk]);
        #pragma unroll
        for (int o = 16; o; o >>= 1) m = fmaxf(m, __shfl_xor_sync(0xffffffffu, m, o));
        float sum = 0.f;
        for (int kk = lane; kk < kmaxb; kk += 32) {
            float e = __expf(S[wq][kk] - m);
            S[wq][kk] = e;
            sum += e;
        }
        #pragma unroll
        for (int o = 16; o; o >>= 1) sum += __shfl_xor_sync(0xffffffffu, sum, o);
        float inv = 1.f / sum;
        for (int kk = lane; kk < kmaxb; kk += 32) S[wq][kk] *= inv;
    }
    __syncthreads();

    float y0 = 0.f, y1 = 0.f;
    for (int kt = 0; kt < ntiles; ++kt) {
        int k0 = kt * 64;
        for (int f = tid; f < 64 * 16; f += 256) {
            int kk = f >> 4, c4 = (f & 15) * 4;
            float4 vv = *(const float4*)(v + (baseRow + k0 + kk) * QKVW + c4);
            *(float4*)&Tl[kk][c4] = vv;
        }
        __syncthreads();
        #pragma unroll 16
        for (int kk = 0; kk < 64; ++kk) {
            float p = S[wq][k0 + kk];
            y0 = fmaf(p, Tl[kk][lane],      y0);
            y1 = fmaf(p, Tl[kk][lane + 32], y1);
        }
        __syncthreads();
    }
    size_t o0 = (baseRow + q0 + wq) * EE + colOff + lane;
    __half h0, l0, h1, l1;
    split_f16(y0, h0, l0);
    split_f16(y1, h1, l1);
    yh[o0]      = h0; yl[o0]      = l0;
    yh[o0 + 32] = h1; yl[o0 + 32] = l1;
}

// ---------------------------------------------------------------------------
// Launch
// ---------------------------------------------------------------------------
extern "C" void kernel_launch(void* const* d_in, const int* in_sizes, int n_in,
                              void* d_out, int out_size)
{
    const int*   x     = (const int*)  d_in[0];
    const float* tok   = (const float*)d_in[2];
    const float* pos   = (const float*)d_in[3];
    const float* ln1g  = (const float*)d_in[4];
    const float* ln1b  = (const float*)d_in[5];
    const float* Wq    = (const float*)d_in[6];
    const float* bq    = (const float*)d_in[7];
    const float* Wk    = (const float*)d_in[8];
    const float* bk    = (const float*)d_in[9];
    const float* Wv    = (const float*)d_in[10];
    const float* bv    = (const float*)d_in[11];
    const float* Wp    = (const float*)d_in[12];
    const float* bp    = (const float*)d_in[13];
    const float* ln2g  = (const float*)d_in[14];
    const float* ln2b  = (const float*)d_in[15];
    const float* Wf1   = (const float*)d_in[16];
    const float* bf1   = (const float*)d_in[17];
    const float* Wf2   = (const float*)d_in[18];
    const float* bf2   = (const float*)d_in[19];
    const float* lnfg  = (const float*)d_in[20];
    const float* lnfb  = (const float*)d_in[21];
    const float* headw = (const float*)d_in[22];
    float* out = (float*)d_out;

    float *h, *qkv;
    cudaGetSymbolAddress((void**)&h,   g_h);
    cudaGetSymbolAddress((void**)&qkv, g_qkv);
    __half *xnh, *xnl, *yh, *yl, *mh, *ml;
    cudaGetSymbolAddress((void**)&xnh, g_xn_h);
    cudaGetSymbolAddress((void**)&xnl, g_xn_l);
    cudaGetSymbolAddress((void**)&yh,  g_y_h);
    cudaGetSymbolAddress((void**)&yl,  g_y_l);
    cudaGetSymbolAddress((void**)&mh,  g_mlp_h);
    cudaGetSymbolAddress((void**)&ml,  g_mlp_l);
    __half *wqkvw, *wpw, *f1w, *f2w, *hdw;
    cudaGetSymbolAddress((void**)&wqkvw, g_wqkvT);
    cudaGetSymbolAddress((void**)&wpw,   g_wpT);
    cudaGetSymbolAddress((void**)&f1w,   g_f1T);
    cudaGetSymbolAddress((void**)&f2w,   g_f2T);
    cudaGetSymbolAddress((void**)&hdw,   g_hdT);

    cudaFuncSetAttribute(mma_gemm, cudaFuncAttributeMaxDynamicSharedMemorySize, GEMM_SMEM);

    const size_t QLS = (size_t)QKVW * EE;
    dim3 wb(32, 8);
    dim3 gQKV(QKVW / 256, MR / 128);
    dim3 gE  (EE   / 256, MR / 128);
    dim3 gF  (FF   / 256, MR / 128);
    dim3 gHd (VV   / 256, MR / 128);

    // weight conversions (fp16 single)
    wconv_kernel<<<dim3(EE / 32, EE / 32, LL), wb>>>(Wq, wqkvw + 0 * (size_t)EE * EE, EE, EE, QLS);
    wconv_kernel<<<dim3(EE / 32, EE / 32, LL), wb>>>(Wk, wqkvw + 1 * (size_t)EE * EE, EE, EE, QLS);
    wconv_kernel<<<dim3(EE / 32, EE / 32, LL), wb>>>(Wv, wqkvw + 2 * (size_t)EE * EE, EE, EE, QLS);
    wconv_kernel<<<dim3(EE / 32, EE / 32, LL), wb>>>(Wp,  wpw, EE, EE, (size_t)EE * EE);
    wconv_kernel<<<dim3(FF / 32, EE / 32, LL), wb>>>(Wf1, f1w, EE, FF, (size_t)EE * FF);
    wconv_kernel<<<dim3(EE / 32, FF / 32, LL), wb>>>(Wf2, f2w, FF, EE, (size_t)EE * FF);
    wconv_kernel<<<dim3(VV / 32, EE / 32, 1 ), wb>>>(headw, hdw, EE, VV, (size_t)EE * VV);

    embed_kernel<<<MR, 256>>>(x, tok, pos, h);

    for (int l = 0; l < LL; ++l) {
        size_t oE  = (size_t)l * EE;
        size_t oQW = (size_t)l * QLS;
        size_t oEE = (size_t)l * EE * EE;
        size_t oF  = (size_t)l * FF;
        size_t oEF = (size_t)l * EE * FF;

        ln_kernel<<<MR, 256>>>(h, ln1g + oE, ln1b + oE, xnh, xnl);

        // qkv = xn @ Wqkv + b{q,k,v}   (fused, N=3072)
        mma_gemm<<<gQKV, 256, GEMM_SMEM>>>(xnh, xnl, wqkvw + oQW,
                                           bq + oE, bk + oE, bv + oE,
                                           nullptr, qkv, nullptr, nullptr,
                                           MR, QKVW, EE, 0);

        attn_kernel<<<BB * HH * (TT / AQ), 256>>>(qkv, yh, yl);

        // h = h + y @ Wp + bp
        mma_gemm<<<gE, 256, GEMM_SMEM>>>(yh, yl, wpw + oEE,
                                         bp + oE, nullptr, nullptr, h, h,
                                         nullptr, nullptr, MR, EE, EE, 0);

        ln_kernel<<<MR, 256>>>(h, ln2g + oE, ln2b + oE, xnh, xnl);

        // mlp = gelu(xn @ Wf1 + bf1)  -> fp16 hi/lo
        mma_gemm<<<gF, 256, GEMM_SMEM>>>(xnh, xnl, f1w + oEF,
                                         bf1 + oF, nullptr, nullptr, nullptr,
                                         nullptr, mh, ml, MR, FF, EE, 1);

        // h = h + mlp @ Wf2 + bf2
        mma_gemm<<<gE, 256, GEMM_SMEM>>>(mh, ml, f2w + oEF,
                                         bf2 + oE, nullptr, nullptr, h, h,
                                         nullptr, nullptr, MR, EE, FF, 0);
    }

    ln_kernel<<<MR, 256>>>(h, lnfg, lnfb, xnh, xnl);
    mma_gemm<<<gHd, 256, GEMM_SMEM>>>(xnh, xnl, hdw,
                                      nullptr, nullptr, nullptr, nullptr,
                                      out, nullptr, nullptr, MR, VV, EE, 0);
}